// round 8
// baseline (speedup 1.0000x reference)
#include <cuda_runtime.h>

// SSIM preservation loss, fully fused, warp-autonomous strips + f32x2 packing.
// clean, adversarial: [32, 3, 512, 512] fp32 -> scalar fp32.
//
// R7 changes (latency-bound at occ=23% per R6 ncu):
//  - 64-thread blocks (2 warps): regs ~92 -> 11 blocks/SM = 22 warps (34% occ)
//  - TH=256, TW=64 -> 1536 blocks, fits in ONE wave (148 SMs x 11 blocks)
//  - split even/odd accumulator chains: serial fma2 depth 11 -> 6 per channel

#define IMG_H 512
#define IMG_W 512
#define N_PLANES (32 * 3)
#define WARPS 2
#define TW (32 * WARPS)         // 64: tile width, one 32-col strip per warp
#define TH 256                  // output rows per block
#define HALO 5
#define NROWS (TH + 2 * HALO)   // 266 h-rows per tile
#define GRID_X (IMG_W / TW)     // 8
#define GRID_Y (IMG_H / TH)     // 2
#define N_BLOCKS (GRID_X * GRID_Y * N_PLANES)  // 1536
#define NPIX 25165824.0         // 32*3*512*512
#define WBUF 44                 // 42 used, padded

// Gaussian window, size 11, sigma 1.5 (normalized).
#define GW0 0.00102838f
#define GW1 0.00759874f
#define GW2 0.03600077f
#define GW3 0.10936068f
#define GW4 0.21300553f
#define GW5 0.26601172f

typedef unsigned long long u64;

__device__ __forceinline__ float gwj(int j) {
    switch (j) {
        case 0: case 10: return GW0;
        case 1: case 9:  return GW1;
        case 2: case 8:  return GW2;
        case 3: case 7:  return GW3;
        case 4: case 6:  return GW4;
        default:         return GW5;
    }
}

__device__ __forceinline__ u64 pack2(float lo, float hi) {
    u64 r; asm("mov.b64 %0, {%1, %2};" : "=l"(r) : "f"(lo), "f"(hi)); return r;
}
__device__ __forceinline__ void unpack2(u64 v, float& lo, float& hi) {
    asm("mov.b64 {%0, %1}, %2;" : "=f"(lo), "=f"(hi) : "l"(v));
}
__device__ __forceinline__ u64 fma2(u64 a, u64 b, u64 c) {
    u64 d; asm("fma.rn.f32x2 %0, %1, %2, %3;" : "=l"(d) : "l"(a), "l"(b), "l"(c)); return d;
}
__device__ __forceinline__ u64 mul2(u64 a, u64 b) {
    u64 d; asm("mul.rn.f32x2 %0, %1, %2;" : "=l"(d) : "l"(a), "l"(b)); return d;
}
__device__ __forceinline__ u64 add2(u64 a, u64 b) {
    u64 d; asm("add.rn.f32x2 %0, %1, %2;" : "=l"(d) : "l"(a), "l"(b)); return d;
}

__device__ float g_part[N_BLOCKS];
__device__ unsigned int g_ticket = 0;

__global__ __launch_bounds__(32 * WARPS)
void ssim_fused_kernel(const float* __restrict__ clean,
                       const float* __restrict__ adv,
                       float* __restrict__ out) {
    __shared__ u64 sbuf[WARPS][2][WBUF];  // per-warp double-buffered halo row
    __shared__ float red[WARPS];
    __shared__ int s_islast;

    const int tid  = threadIdx.x;
    const int warp = tid >> 5;
    const int lane = tid & 31;
    const int colBase = blockIdx.x * TW + warp * 32;
    const int tileY   = blockIdx.y * TH;
    const size_t plane = (size_t)blockIdx.z * (size_t)(IMG_H * IMG_W);
    const float* __restrict__ cp = clean + plane;
    const float* __restrict__ ap = adv + plane;

    const int gx0 = colBase - HALO + lane;
    const int gx1 = gx0 + 32;                     // lanes 0..9 only
    const bool x0ok = (unsigned)gx0 < IMG_W;
    const bool x1ok = (lane < 10) && ((unsigned)gx1 < IMG_W);

    // vertical ring (slot = r % 11): rv=(hx,hy), rs=(hxx,hyy), rxy scalar
    u64 rv[11], rs[11];
    float rxy[11];
    float acc = 0.0f;

    // ---- prefetch row 0 (gy = tileY - HALO) ----
    float pc0, pa0, pc1, pa1;
    {
        const int gy = tileY - HALO;
        const bool yok = (unsigned)gy < IMG_H;
        const size_t rowoff = (size_t)gy * IMG_W;
        pc0 = (yok && x0ok) ? __ldg(cp + rowoff + gx0) : 0.0f;
        pa0 = (yok && x0ok) ? __ldg(ap + rowoff + gx0) : 0.0f;
        pc1 = (yok && x1ok) ? __ldg(cp + rowoff + gx1) : 0.0f;
        pa1 = (yok && x1ok) ? __ldg(ap + rowoff + gx1) : 0.0f;
    }

    for (int rb = 0; rb < NROWS; rb += 11) {
#pragma unroll
        for (int t = 0; t < 11; ++t) {
            const int r = rb + t;           // h-row index; r % 11 == t
            if (r >= NROWS) break;          // uniform across block

            // ---- commit prefetched row r to this warp's shared buffer ----
            u64* buf = sbuf[warp][r & 1];
            buf[lane] = pack2(pc0, pa0);
            if (lane < 10) buf[lane + 32] = pack2(pc1, pa1);
            __syncwarp();

            // ---- issue prefetch for row r+1 (hidden behind compute) ----
            {
                const int gy = tileY + (r + 1) - HALO;
                const bool yok = (r + 1 < NROWS) && ((unsigned)gy < IMG_H);
                const size_t rowoff = (size_t)gy * IMG_W;
                pc0 = (yok && x0ok) ? __ldg(cp + rowoff + gx0) : 0.0f;
                pa0 = (yok && x0ok) ? __ldg(ap + rowoff + gx0) : 0.0f;
                pc1 = (yok && x1ok) ? __ldg(cp + rowoff + gx1) : 0.0f;
                pa1 = (yok && x1ok) ? __ldg(ap + rowoff + gx1) : 0.0f;
            }

            // ---- horizontal blur: packed channels, split even/odd chains ----
            u64 hva = 0ull, hvb = 0ull, hsa = 0ull, hsb = 0ull;
            float hxya = 0.0f, hxyb = 0.0f;
#pragma unroll
            for (int j = 0; j < 11; ++j) {
                const u64 v = buf[lane + j];
                float x, y; unpack2(v, x, y);
                const u64 w2 = pack2(gwj(j), gwj(j));   // folds to constant
                if (j & 1) {
                    hvb  = fma2(w2, v, hvb);
                    hsb  = fma2(w2, mul2(v, v), hsb);
                    hxyb = fmaf(gwj(j), x * y, hxyb);
                } else {
                    hva  = fma2(w2, v, hva);
                    hsa  = fma2(w2, mul2(v, v), hsa);
                    hxya = fmaf(gwj(j), x * y, hxya);
                }
            }
            rv[t] = add2(hva, hvb);
            rs[t] = add2(hsa, hsb);
            rxy[t] = hxya + hxyb;

            // ---- vertical blur + SSIM once ring is full ----
            if (r >= 2 * HALO) {
                u64 mva = 0ull, mvb = 0ull, eva = 0ull, evb = 0ull;
                float e12a = 0.0f, e12b = 0.0f;
#pragma unroll
                for (int j = 0; j < 11; ++j) {
                    const int s = (t + 1 + j) % 11;   // compile-time
                    const u64 w2 = pack2(gwj(j), gwj(j));
                    if (j & 1) {
                        mvb  = fma2(w2, rv[s], mvb);
                        evb  = fma2(w2, rs[s], evb);
                        e12b = fmaf(gwj(j), rxy[s], e12b);
                    } else {
                        mva  = fma2(w2, rv[s], mva);
                        eva  = fma2(w2, rs[s], eva);
                        e12a = fmaf(gwj(j), rxy[s], e12a);
                    }
                }
                float m1, m2, e11, e22;
                unpack2(add2(mva, mvb), m1, m2);
                unpack2(add2(eva, evb), e11, e22);
                const float e12 = e12a + e12b;
                const float C1 = 1e-4f, C2 = 9e-4f;
                const float m1s = m1 * m1;
                const float m2s = m2 * m2;
                const float m12 = m1 * m2;
                const float s1  = e11 - m1s;
                const float s2  = e22 - m2s;
                const float s12 = e12 - m12;
                const float num = fmaf(2.0f, m12, C1) * fmaf(2.0f, s12, C2);
                const float den = (m1s + m2s + C1) * (s1 + s2 + C2);
                acc += __fdividef(num, den);
            }
        }
    }

    // ---- block reduction -> deterministic per-block partial ----
#pragma unroll
    for (int o = 16; o; o >>= 1)
        acc += __shfl_down_sync(0xffffffffu, acc, o);
    if (lane == 0) red[warp] = acc;
    __syncthreads();

    const int bid = blockIdx.x + GRID_X * (blockIdx.y + GRID_Y * blockIdx.z);
    if (tid == 0) {
        float s = red[0] + red[1];
        g_part[bid] = s;
        __threadfence();
        unsigned int old = atomicAdd(&g_ticket, 1u);
        s_islast = (old == N_BLOCKS - 1) ? 1 : 0;
    }
    __syncthreads();

    // ---- last block computes the global mean ----
    if (s_islast) {
        __shared__ double sred[WARPS];
        volatile float* vp = g_part;
        double s = 0.0;
        for (int i = tid; i < N_BLOCKS; i += 32 * WARPS) s += (double)vp[i];
#pragma unroll
        for (int o = 16; o; o >>= 1)
            s += __shfl_down_sync(0xffffffffu, s, o);
        if (lane == 0) sred[warp] = s;
        __syncthreads();
        if (tid == 0) {
            double tot = sred[0] + sred[1];
            out[0] = 1.0f - (float)(tot / NPIX);
            g_ticket = 0;                      // reset for next graph replay
        }
    }
}

extern "C" void kernel_launch(void* const* d_in, const int* in_sizes, int n_in,
                              void* d_out, int out_size) {
    (void)in_sizes; (void)n_in; (void)out_size;
    const float* clean = (const float*)d_in[0];
    const float* adv   = (const float*)d_in[1];
    float* out = (float*)d_out;

    dim3 grid(GRID_X, GRID_Y, N_PLANES);
    ssim_fused_kernel<<<grid, 32 * WARPS>>>(clean, adv, out);
}

// round 9
// speedup vs baseline: 1.2563x; 1.2563x over previous
#include <cuda_runtime.h>

// SSIM preservation loss, fully fused, warp-autonomous strips + f32x2 packing.
// clean, adversarial: [32, 3, 512, 512] fp32 -> scalar fp32.
//
// R9: occupancy-focused geometry. 128-thread blocks (4 warps) with
// __launch_bounds__(128,5): reg granularity gives 5 blocks/SM = 20 warps (31%)
// vs 16 warps for 256-thread blocks. TW=TH=128, grid (4,4,96)=1536 blocks
// (~2 waves of 740 resident). Single accumulator chains (reg-lean, R8's split
// chains cost 10 regs for no gain).

#define IMG_H 512
#define IMG_W 512
#define N_PLANES (32 * 3)
#define WARPS 4
#define TW (32 * WARPS)         // 128
#define TH 128                  // output rows per block
#define HALO 5
#define NROWS (TH + 2 * HALO)   // 138 h-rows per tile
#define GRID_X (IMG_W / TW)     // 4
#define GRID_Y (IMG_H / TH)     // 4
#define N_BLOCKS (GRID_X * GRID_Y * N_PLANES)  // 1536
#define NPIX 25165824.0         // 32*3*512*512
#define WBUF 44                 // 42 used, padded

// Gaussian window, size 11, sigma 1.5 (normalized).
#define GW0 0.00102838f
#define GW1 0.00759874f
#define GW2 0.03600077f
#define GW3 0.10936068f
#define GW4 0.21300553f
#define GW5 0.26601172f

typedef unsigned long long u64;

__device__ __forceinline__ float gwj(int j) {
    switch (j) {
        case 0: case 10: return GW0;
        case 1: case 9:  return GW1;
        case 2: case 8:  return GW2;
        case 3: case 7:  return GW3;
        case 4: case 6:  return GW4;
        default:         return GW5;
    }
}

__device__ __forceinline__ u64 pack2(float lo, float hi) {
    u64 r; asm("mov.b64 %0, {%1, %2};" : "=l"(r) : "f"(lo), "f"(hi)); return r;
}
__device__ __forceinline__ void unpack2(u64 v, float& lo, float& hi) {
    asm("mov.b64 {%0, %1}, %2;" : "=f"(lo), "=f"(hi) : "l"(v));
}
__device__ __forceinline__ u64 fma2(u64 a, u64 b, u64 c) {
    u64 d; asm("fma.rn.f32x2 %0, %1, %2, %3;" : "=l"(d) : "l"(a), "l"(b), "l"(c)); return d;
}
__device__ __forceinline__ u64 mul2(u64 a, u64 b) {
    u64 d; asm("mul.rn.f32x2 %0, %1, %2;" : "=l"(d) : "l"(a), "l"(b)); return d;
}

__device__ float g_part[N_BLOCKS];
__device__ unsigned int g_ticket = 0;

__global__ __launch_bounds__(32 * WARPS, 5)
void ssim_fused_kernel(const float* __restrict__ clean,
                       const float* __restrict__ adv,
                       float* __restrict__ out) {
    __shared__ u64 sbuf[WARPS][2][WBUF];  // per-warp double-buffered halo row
    __shared__ float red[WARPS];
    __shared__ int s_islast;

    const int tid  = threadIdx.x;
    const int warp = tid >> 5;
    const int lane = tid & 31;
    const int colBase = blockIdx.x * TW + warp * 32;
    const int tileY   = blockIdx.y * TH;
    const size_t plane = (size_t)blockIdx.z * (size_t)(IMG_H * IMG_W);
    const float* __restrict__ cp = clean + plane;
    const float* __restrict__ ap = adv + plane;

    const int gx0 = colBase - HALO + lane;
    const int gx1 = gx0 + 32;                     // lanes 0..9 only
    const bool x0ok = (unsigned)gx0 < IMG_W;
    const bool x1ok = (lane < 10) && ((unsigned)gx1 < IMG_W);

    // vertical ring (slot = r % 11): rv=(hx,hy), rs=(hxx,hyy), rxy scalar
    u64 rv[11], rs[11];
    float rxy[11];
    float acc = 0.0f;

    // ---- prefetch row 0 (gy = tileY - HALO) ----
    float pc0, pa0, pc1, pa1;
    {
        const int gy = tileY - HALO;
        const bool yok = (unsigned)gy < IMG_H;
        const size_t rowoff = (size_t)gy * IMG_W;
        pc0 = (yok && x0ok) ? __ldg(cp + rowoff + gx0) : 0.0f;
        pa0 = (yok && x0ok) ? __ldg(ap + rowoff + gx0) : 0.0f;
        pc1 = (yok && x1ok) ? __ldg(cp + rowoff + gx1) : 0.0f;
        pa1 = (yok && x1ok) ? __ldg(ap + rowoff + gx1) : 0.0f;
    }

    for (int rb = 0; rb < NROWS; rb += 11) {
#pragma unroll
        for (int t = 0; t < 11; ++t) {
            const int r = rb + t;           // h-row index; r % 11 == t
            if (r >= NROWS) break;          // uniform across block

            // ---- commit prefetched row r to this warp's shared buffer ----
            u64* buf = sbuf[warp][r & 1];
            buf[lane] = pack2(pc0, pa0);
            if (lane < 10) buf[lane + 32] = pack2(pc1, pa1);
            __syncwarp();

            // ---- issue prefetch for row r+1 (hidden behind compute) ----
            {
                const int gy = tileY + (r + 1) - HALO;
                const bool yok = (r + 1 < NROWS) && ((unsigned)gy < IMG_H);
                const size_t rowoff = (size_t)gy * IMG_W;
                pc0 = (yok && x0ok) ? __ldg(cp + rowoff + gx0) : 0.0f;
                pa0 = (yok && x0ok) ? __ldg(ap + rowoff + gx0) : 0.0f;
                pc1 = (yok && x1ok) ? __ldg(cp + rowoff + gx1) : 0.0f;
                pa1 = (yok && x1ok) ? __ldg(ap + rowoff + gx1) : 0.0f;
            }

            // ---- horizontal blur: packed (x,y) & (x2,y2), scalar xy ----
            u64 hv = 0ull, hs = 0ull;
            float hxy = 0.0f;
#pragma unroll
            for (int j = 0; j < 11; ++j) {
                const u64 v = buf[lane + j];
                float x, y; unpack2(v, x, y);
                const u64 w2 = pack2(gwj(j), gwj(j));   // folds to constant
                hv  = fma2(w2, v, hv);
                hs  = fma2(w2, mul2(v, v), hs);
                hxy = fmaf(gwj(j), x * y, hxy);
            }
            rv[t] = hv; rs[t] = hs; rxy[t] = hxy;

            // ---- vertical blur + SSIM once ring is full ----
            if (r >= 2 * HALO) {
                u64 mv = 0ull, ev = 0ull;     // (m1,m2), (e11,e22)
                float e12 = 0.0f;
#pragma unroll
                for (int j = 0; j < 11; ++j) {
                    const int s = (t + 1 + j) % 11;   // compile-time
                    const u64 w2 = pack2(gwj(j), gwj(j));
                    mv  = fma2(w2, rv[s], mv);
                    ev  = fma2(w2, rs[s], ev);
                    e12 = fmaf(gwj(j), rxy[s], e12);
                }
                float m1, m2, e11, e22;
                unpack2(mv, m1, m2);
                unpack2(ev, e11, e22);
                const float C1 = 1e-4f, C2 = 9e-4f;
                const float m1s = m1 * m1;
                const float m2s = m2 * m2;
                const float m12 = m1 * m2;
                const float s1  = e11 - m1s;
                const float s2  = e22 - m2s;
                const float s12 = e12 - m12;
                const float num = fmaf(2.0f, m12, C1) * fmaf(2.0f, s12, C2);
                const float den = (m1s + m2s + C1) * (s1 + s2 + C2);
                acc += __fdividef(num, den);
            }
        }
    }

    // ---- block reduction -> deterministic per-block partial ----
#pragma unroll
    for (int o = 16; o; o >>= 1)
        acc += __shfl_down_sync(0xffffffffu, acc, o);
    if (lane == 0) red[warp] = acc;
    __syncthreads();

    const int bid = blockIdx.x + GRID_X * (blockIdx.y + GRID_Y * blockIdx.z);
    if (tid == 0) {
        float s = 0.0f;
#pragma unroll
        for (int w = 0; w < WARPS; ++w) s += red[w];
        g_part[bid] = s;
        __threadfence();
        unsigned int old = atomicAdd(&g_ticket, 1u);
        s_islast = (old == N_BLOCKS - 1) ? 1 : 0;
    }
    __syncthreads();

    // ---- last block computes the global mean ----
    if (s_islast) {
        __shared__ double sred[WARPS];
        volatile float* vp = g_part;
        double s = 0.0;
        for (int i = tid; i < N_BLOCKS; i += 32 * WARPS) s += (double)vp[i];
#pragma unroll
        for (int o = 16; o; o >>= 1)
            s += __shfl_down_sync(0xffffffffu, s, o);
        if (lane == 0) sred[warp] = s;
        __syncthreads();
        if (tid == 0) {
            double tot = 0.0;
#pragma unroll
            for (int w = 0; w < WARPS; ++w) tot += sred[w];
            out[0] = 1.0f - (float)(tot / NPIX);
            g_ticket = 0;                      // reset for next graph replay
        }
    }
}

extern "C" void kernel_launch(void* const* d_in, const int* in_sizes, int n_in,
                              void* d_out, int out_size) {
    (void)in_sizes; (void)n_in; (void)out_size;
    const float* clean = (const float*)d_in[0];
    const float* adv   = (const float*)d_in[1];
    float* out = (float*)d_out;

    dim3 grid(GRID_X, GRID_Y, N_PLANES);
    ssim_fused_kernel<<<grid, 32 * WARPS>>>(clean, adv, out);
}